// round 6
// baseline (speedup 1.0000x reference)
#include <cuda_runtime.h>
#include <cstdint>

#define HW    65536
#define NQ    100
#define NT    32
#define NB    8
#define NROWP 112   // 7 mtiles * 16

// ---------------- device scratch ----------------
__device__ uint32_t g_bits[NB * HW];
__device__ float    g_tsum[NB * NT];
__device__ float    g_dotPM[NB * NROWP * NT];
__device__ float    g_dotSIG[NB * NROWP * NT];
__device__ float    g_sumSP[NB * NROWP];
__device__ float    g_sumSIG[NB * NROWP];
__device__ float    g_classT[NB * NT * NQ];
__device__ float    g_costT[NB * NT * NQ];   // [b][t][n]

// ---------------- helpers ----------------
__device__ __forceinline__ uint32_t pack_bf16(float hi, float lo) {
    uint32_t d;
    asm("cvt.rn.bf16x2.f32 %0, %1, %2;" : "=r"(d) : "f"(hi), "f"(lo));
    return d;
}

__device__ __forceinline__ void mma_bf16(float* c, const uint32_t* a,
                                         uint32_t b0, uint32_t b1) {
    asm volatile(
        "mma.sync.aligned.m16n8k16.row.col.f32.bf16.bf16.f32 "
        "{%0,%1,%2,%3}, {%4,%5,%6,%7}, {%8,%9}, {%0,%1,%2,%3};"
        : "+f"(c[0]), "+f"(c[1]), "+f"(c[2]), "+f"(c[3])
        : "r"(a[0]), "r"(a[1]), "r"(a[2]), "r"(a[3]), "r"(b0), "r"(b1));
}

// sigmoid + softplus via MUFU.TANH (2 MUFU instead of 3):
//   sigmoid(|x|) = 0.5*tanh(|x|/2) + 0.5
//   softplus(x)  = max(x,0) + log(1+e^-|x|) = max(x,0) - log(sigmoid(|x|))
__device__ __forceinline__ void elem_math(float x, float& sig, float& sp) {
    float ax = fabsf(x);
    float th;
    asm("tanh.approx.f32 %0, %1;" : "=f"(th) : "f"(ax * 0.5f));
    float sa = fmaf(th, 0.5f, 0.5f);
    sig = (x >= 0.0f) ? sa : 1.0f - sa;
    sp  = fmaxf(x, 0.0f) - __logf(sa);
}

// order-preserving float<->uint32 key
__device__ __forceinline__ uint32_t fkey(float f) {
    uint32_t u = __float_as_uint(f);
    return (u & 0x80000000u) ? ~u : (u | 0x80000000u);
}
__device__ __forceinline__ float fkey_inv(uint32_t k) {
    uint32_t u = (k & 0x80000000u) ? (k ^ 0x80000000u) : ~k;
    return __uint_as_float(u);
}
__device__ __forceinline__ int sel4i(int a0, int a1, int a2, int a3, int s) {
    return s == 0 ? a0 : s == 1 ? a1 : s == 2 ? a2 : a3;
}

// ---------------- kernel 1: class cost (+ accumulator zeroing) ----------------
__global__ void k_class(const float* __restrict__ logits,
                        const int* __restrict__ labels) {
    // fold in zeroing of accumulators (runs before k_tmask / k_main)
    int gid = blockIdx.x * 32 + threadIdx.x;            // 25600 threads
    for (int i = gid; i < NB * NROWP * NT; i += NB * NQ * 32) {
        g_dotPM[i] = 0.f; g_dotSIG[i] = 0.f;
    }
    if (gid < NB * NROWP) { g_sumSP[gid] = 0.f; g_sumSIG[gid] = 0.f; }
    if (gid < NB * NT)    { g_tsum[gid] = 0.f; }

    int b = blockIdx.x / NQ, n = blockIdx.x % NQ;
    int lane = threadIdx.x;
    __shared__ float sh[81];
    const float* L = logits + (size_t)(b * NQ + n) * 81;

    float x0 = L[lane];
    float x1 = (lane + 32 < 81) ? L[lane + 32] : -1e30f;
    float x2 = (lane + 64 < 81) ? L[lane + 64] : -1e30f;
    float m = fmaxf(x0, fmaxf(x1, x2));
    #pragma unroll
    for (int o = 16; o; o >>= 1) m = fmaxf(m, __shfl_xor_sync(0xffffffffu, m, o));

    float e0 = __expf(x0 - m);
    float e1 = (lane + 32 < 81) ? __expf(x1 - m) : 0.f;
    float e2 = (lane + 64 < 81) ? __expf(x2 - m) : 0.f;
    float s = e0 + e1 + e2;
    #pragma unroll
    for (int o = 16; o; o >>= 1) s += __shfl_xor_sync(0xffffffffu, s, o);

    sh[lane] = e0;
    if (lane + 32 < 81) sh[lane + 32] = e1;
    if (lane + 64 < 81) sh[lane + 64] = e2;
    __syncwarp();

    float inv = 1.0f / s;
    int lbl = labels[b * NT + lane];
    g_classT[(b * NT + lane) * NQ + n] = -sh[lbl] * inv;
}

// ---------------- kernel 2: target mask preprocess ----------------
// 2 pixels per thread via one float4 per target (elements .x and .z are the
// even columns). Same DRAM sector traffic, half the load instructions.
__global__ __launch_bounds__(256) void k_tmask(const float* __restrict__ tgt) {
    int b = blockIdx.y;
    int p0 = blockIdx.x * 512 + threadIdx.x * 2;
    int h = p0 >> 8, w = p0 & 255;                    // w even
    size_t base = ((size_t)b * NT) * 262144 + (size_t)(2 * h) * 512 + 2 * w;
    uint32_t w0 = 0, w1 = 0;
    #pragma unroll
    for (int t = 0; t < 32; ++t) {
        float4 v = *(const float4*)(tgt + base + (size_t)t * 262144);
        w0 |= (uint32_t)(v.x != 0.0f) << t;
        w1 |= (uint32_t)(v.z != 0.0f) << t;
    }
    *(uint2*)(g_bits + b * HW + p0) = make_uint2(w0, w1);

    int lane = threadIdx.x & 31;
    int cnt = 0;
    #pragma unroll
    for (int t = 0; t < 32; ++t) {
        unsigned m0 = __ballot_sync(0xffffffffu, (w0 >> t) & 1u);
        unsigned m1 = __ballot_sync(0xffffffffu, (w1 >> t) & 1u);
        if (lane == t) cnt = __popc(m0) + __popc(m1);
    }
    atomicAdd(&g_tsum[b * NT + lane], (float)cnt);
}

// ---------------- kernel 3: fused elementwise + dual bf16 MMA ----------------
__global__ __launch_bounds__(256, 4) void k_main(const float* __restrict__ pm) {
    const int b = blockIdx.z, mt = blockIdx.y;
    const int warp = threadIdx.x >> 5, lane = threadIdx.x & 31;
    const int kstart = blockIdx.x * (HW / 16) + warp * (HW / 16 / 8);
    const int rq = lane >> 2;
    const int kq = (lane & 3) << 1;
    const int r_lo = mt * 16 + rq, r_hi = r_lo + 8;
    const int rl = min(r_lo, NQ - 1), rh = min(r_hi, NQ - 1);

    const float*    pmb = pm + (size_t)b * NQ * HW;
    const uint32_t* bw  = g_bits + b * HW;

    float cpm[4][4], csg[4][4];
    #pragma unroll
    for (int i = 0; i < 4; ++i)
        #pragma unroll
        for (int j = 0; j < 4; ++j) { cpm[i][j] = 0.f; csg[i][j] = 0.f; }

    float ssp0 = 0.f, ssp1 = 0.f, ssg0 = 0.f, ssg1 = 0.f;

    #pragma unroll 4
    for (int it = 0; it < 32; ++it) {
        int k0 = kstart + it * 16 + kq;
        float2 x00 = *(const float2*)(pmb + (size_t)rl * HW + k0);
        float2 x10 = *(const float2*)(pmb + (size_t)rh * HW + k0);
        float2 x01 = *(const float2*)(pmb + (size_t)rl * HW + k0 + 8);
        float2 x11 = *(const float2*)(pmb + (size_t)rh * HW + k0 + 8);
        uint2 wa = *(const uint2*)(bw + k0);
        uint2 wb = *(const uint2*)(bw + k0 + 8);

        float s00a, s00b, s10a, s10b, s01a, s01b, s11a, s11b;
        float p00a, p00b, p10a, p10b, p01a, p01b, p11a, p11b;
        elem_math(x00.x, s00a, p00a); elem_math(x00.y, s00b, p00b);
        elem_math(x10.x, s10a, p10a); elem_math(x10.y, s10b, p10b);
        elem_math(x01.x, s01a, p01a); elem_math(x01.y, s01b, p01b);
        elem_math(x11.x, s11a, p11a); elem_math(x11.y, s11b, p11b);

        ssp0 += (p00a + p00b) + (p01a + p01b);
        ssp1 += (p10a + p10b) + (p11a + p11b);
        ssg0 += (s00a + s00b) + (s01a + s01b);
        ssg1 += (s10a + s10b) + (s11a + s11b);

        uint32_t apm[4] = { pack_bf16(x00.y, x00.x), pack_bf16(x10.y, x10.x),
                            pack_bf16(x01.y, x01.x), pack_bf16(x11.y, x11.x) };
        uint32_t asg[4] = { pack_bf16(s00b, s00a), pack_bf16(s10b, s10a),
                            pack_bf16(s01b, s01a), pack_bf16(s11b, s11a) };

        uint32_t t0 = wa.x >> rq, t1 = wa.y >> rq;
        uint32_t t2 = wb.x >> rq, t3 = wb.y >> rq;
        #pragma unroll
        for (int nt = 0; nt < 4; ++nt) {
            uint32_t b0 = ((t0 >> (8 * nt)) & 1u) * 0x3F80u |
                          ((t1 >> (8 * nt)) & 1u) * 0x3F800000u;
            uint32_t b1 = ((t2 >> (8 * nt)) & 1u) * 0x3F80u |
                          ((t3 >> (8 * nt)) & 1u) * 0x3F800000u;
            mma_bf16(cpm[nt], apm, b0, b1);
            mma_bf16(csg[nt], asg, b0, b1);
        }
    }

    int base_lo = (b * NROWP + r_lo) * NT;
    int base_hi = (b * NROWP + r_hi) * NT;
    #pragma unroll
    for (int nt = 0; nt < 4; ++nt) {
        int c = nt * 8 + kq;
        atomicAdd(&g_dotPM[base_lo + c],     cpm[nt][0]);
        atomicAdd(&g_dotPM[base_lo + c + 1], cpm[nt][1]);
        atomicAdd(&g_dotPM[base_hi + c],     cpm[nt][2]);
        atomicAdd(&g_dotPM[base_hi + c + 1], cpm[nt][3]);
        atomicAdd(&g_dotSIG[base_lo + c],     csg[nt][0]);
        atomicAdd(&g_dotSIG[base_lo + c + 1], csg[nt][1]);
        atomicAdd(&g_dotSIG[base_hi + c],     csg[nt][2]);
        atomicAdd(&g_dotSIG[base_hi + c + 1], csg[nt][3]);
    }
    atomicAdd(&g_sumSP[b * NROWP + r_lo],  ssp0);
    atomicAdd(&g_sumSP[b * NROWP + r_hi],  ssp1);
    atomicAdd(&g_sumSIG[b * NROWP + r_lo], ssg0);
    atomicAdd(&g_sumSIG[b * NROWP + r_hi], ssg1);
}

// ---------------- kernel 4: assemble transposed cost matrix ----------------
__global__ void k_cost() {
    int i = blockIdx.x * 256 + threadIdx.x;
    if (i >= NB * NT * NQ) return;
    int n = i % NQ;
    int t = (i / NQ) % NT;
    int b = i / (NQ * NT);
    float spm  = g_sumSP[b * NROWP + n] * (1.0f / HW);
    float dpm  = g_dotPM[(b * NROWP + n) * NT + t] * (1.0f / HW);
    float dsg  = g_dotSIG[(b * NROWP + n) * NT + t];
    float den  = g_sumSIG[b * NROWP + n] + g_tsum[b * NT + t] + 1.0f;
    float dice = 1.0f - (2.0f * dsg + 1.0f) / den;
    g_costT[i] = g_classT[i] + (spm - dpm) + dice;
}

// ---------------- kernel 5: Hungarian (JV), one warp per batch ----------------
__global__ void k_hung(float* __restrict__ out) {
    const int b = blockIdx.x;
    const int lane = threadIdx.x;
    __shared__ float Cs[NT * NQ];
    __shared__ float u[NT + 1];
    __shared__ int   psh[NQ + 1];

    for (int idx = lane; idx < NT * NQ; idx += 32)
        Cs[idx] = g_costT[b * NT * NQ + idx];
    if (lane <= NT) u[lane] = 0.f;
    __syncwarp();

    float v0 = 0.f, v1 = 0.f, v2 = 0.f, v3 = 0.f;
    int   p0 = 0, p1 = 0, p2 = 0, p3 = 0;
    int   w0 = 0, w1 = 0, w2 = 0, w3 = 0;

    for (int i = 1; i <= NT; ++i) {
        float m0 = 1e30f, m1 = 1e30f, m2 = 1e30f, m3 = 1e30f;
        unsigned usedm = 0;
        if (lane == 0) p0 = i;
        int j0 = 0;

        while (true) {
            if ((j0 & 31) == lane) usedm |= 1u << (j0 >> 5);
            int i0 = __shfl_sync(0xffffffffu, sel4i(p0, p1, p2, p3, j0 >> 5), j0 & 31);
            float ui0 = u[i0];
            const float* Crow = Cs + (i0 - 1) * NQ;

            uint32_t bk = 0xFFFFFFFFu; int bj = 127;
            if (lane >= 1 && !(usedm & 1u)) {
                float cur = Crow[lane - 1] - ui0 - v0;
                if (cur < m0) { m0 = cur; w0 = j0; }
                uint32_t k = fkey(m0);
                if (k < bk) { bk = k; bj = lane; }
            }
            if (!(usedm & 2u)) {
                float cur = Crow[31 + lane] - ui0 - v1;
                if (cur < m1) { m1 = cur; w1 = j0; }
                uint32_t k = fkey(m1);
                if (k < bk) { bk = k; bj = 32 + lane; }
            }
            if (!(usedm & 4u)) {
                float cur = Crow[63 + lane] - ui0 - v2;
                if (cur < m2) { m2 = cur; w2 = j0; }
                uint32_t k = fkey(m2);
                if (k < bk) { bk = k; bj = 64 + lane; }
            }
            if (lane <= 4 && !(usedm & 8u)) {
                float cur = Crow[95 + lane] - ui0 - v3;
                if (cur < m3) { m3 = cur; w3 = j0; }
                uint32_t k = fkey(m3);
                if (k < bk) { bk = k; bj = 96 + lane; }
            }

            uint32_t kmin = __reduce_min_sync(0xffffffffu, bk);
            unsigned ball = __ballot_sync(0xffffffffu, bk == kmin);
            int src = __ffs(ball) - 1;
            int j1  = __shfl_sync(0xffffffffu, bj, src);
            float delta = fkey_inv(kmin);

            if (usedm & 1u) { u[p0] += delta; v0 -= delta; } else m0 -= delta;
            if (usedm & 2u) { u[p1] += delta; v1 -= delta; } else m1 -= delta;
            if (usedm & 4u) { u[p2] += delta; v2 -= delta; } else m2 -= delta;
            if (usedm & 8u) { u[p3] += delta; v3 -= delta; } else m3 -= delta;
            __syncwarp();

            j0 = j1;
            int pj0 = __shfl_sync(0xffffffffu, sel4i(p0, p1, p2, p3, j0 >> 5), j0 & 31);
            if (pj0 == 0) break;
        }

        while (j0 != 0) {
            int j1  = __shfl_sync(0xffffffffu, sel4i(w0, w1, w2, w3, j0 >> 5), j0 & 31);
            int pj1 = __shfl_sync(0xffffffffu, sel4i(p0, p1, p2, p3, j1 >> 5), j1 & 31);
            if ((j0 & 31) == lane) {
                int s = j0 >> 5;
                if (s == 0) p0 = pj1; else if (s == 1) p1 = pj1;
                else if (s == 2) p2 = pj1; else p3 = pj1;
            }
            j0 = j1;
        }
        __syncwarp();
    }

    psh[lane] = p0;
    psh[32 + lane] = p1;
    psh[64 + lane] = p2;
    if (lane <= 4) psh[96 + lane] = p3;
    __syncwarp();

    if (lane == 0) {
        int k = 0;
        for (int j = 1; j <= NQ; ++j) {
            if (psh[j]) {
                out[b * NT + k]           = (float)(j - 1);
                out[NB * NT + b * NT + k] = (float)(psh[j] - 1);
                ++k;
            }
        }
    }
}

// ---------------- launch ----------------
extern "C" void kernel_launch(void* const* d_in, const int* in_sizes, int n_in,
                              void* d_out, int out_size) {
    const float* logits = nullptr;
    const float* pmask  = nullptr;
    const float* tmask  = nullptr;
    const int*   labels = nullptr;

    for (int i = 0; i < n_in; ++i) {
        switch (in_sizes[i]) {
            case 64800:    logits = (const float*)d_in[i]; break;
            case 52428800: pmask  = (const float*)d_in[i]; break;
            case 256:      labels = (const int*)d_in[i];   break;
            default:
                if (in_sizes[i] == 67108864) tmask = (const float*)d_in[i];
                break;
        }
    }
    float* out = (float*)d_out;

    k_class<<<NB * NQ, 32>>>(logits, labels);
    k_tmask<<<dim3(HW / 512, NB), 256>>>(tmask);
    k_main<<<dim3(16, 7, NB), 256>>>(pmask);
    k_cost<<<(NB * NT * NQ + 255) / 256, 256>>>();
    k_hung<<<NB, 32>>>(out);
}